// round 5
// baseline (speedup 1.0000x reference)
#include <cuda_runtime.h>
#include <math.h>

#define NB  16
#define C   256
#define H   80
#define W   80
#define MIP 8
#define L   160            // H + W
#define BN_EPS 1e-5f

#define K1_PPB   4                         // planes per block in k1
#define K3_BLK   1280
#define K3_THR   256
#define K3_STRIDE (K3_BLK * K3_THR)        // 327680
#define N4_TOTAL (NB * C * H * W / 4)      // 6,553,600 float4
#define K3_ITER  (N4_TOTAL / K3_STRIDE)    // exactly 20

// Scratch (device globals: no allocations allowed)
__device__ float g_y [NB * C * L];   // [n][c][l]: l<80 row means (x_h), l>=80 col means (x_w)
__device__ float g_ah[NB * C * H];
__device__ float g_aw[NB * C * W];

__device__ __forceinline__ float fsig(float v) { return 1.f / (1.f + __expf(-v)); }

// ---------------------------------------------------------------------------
// k1: 320 threads, K1_PPB planes per block (sequential). 20 col-groups x 16
// row-groups; column partials in registers, tiny partials through padded smem.
// ---------------------------------------------------------------------------
__global__ __launch_bounds__(320) void k1_means(const float* __restrict__ x) {
    __shared__ float s_row[H][21];     // 21: gcd(21,32)=1
    __shared__ float s_col[W][17];     // 17: gcd(17,32)=1
    const int t  = threadIdx.x;
    const int q  = t % 20;             // float4 column group
    const int rg = t / 20;             // row group 0..15
    const float inv80 = 1.0f / 80.0f;

    for (int p = 0; p < K1_PPB; p++) {
        const int plane = blockIdx.x * K1_PPB + p;
        const float4* __restrict__ xp = (const float4*)(x + (size_t)plane * (H * W));

        float4 cacc = make_float4(0.f, 0.f, 0.f, 0.f);
        #pragma unroll
        for (int i = 0; i < 5; i++) {
            int r = i * 16 + rg;
            float4 v = xp[r * 20 + q];
            cacc.x += v.x; cacc.y += v.y; cacc.z += v.z; cacc.w += v.w;
            s_row[r][q] = v.x + v.y + v.z + v.w;
        }
        s_col[4 * q + 0][rg] = cacc.x;
        s_col[4 * q + 1][rg] = cacc.y;
        s_col[4 * q + 2][rg] = cacc.z;
        s_col[4 * q + 3][rg] = cacc.w;
        __syncthreads();

        if (t < H) {
            float s = 0.f;
            #pragma unroll
            for (int j = 0; j < 20; j++) s += s_row[t][j];
            g_y[(size_t)plane * L + t] = s * inv80;          // x_h (row mean)
        } else if (t >= 160 && t < 160 + W) {
            int col = t - 160;
            float s = 0.f;
            #pragma unroll
            for (int g = 0; g < 16; g++) s += s_col[col][g];
            g_y[(size_t)plane * L + H + col] = s * inv80;    // x_w (col mean)
        }
        __syncthreads();                                     // smem reuse guard
    }
}

// ---------------------------------------------------------------------------
// k2: grid (16, 2), block 320. GEMM1 coalesced over l; GEMM2 register-hoisted.
// ---------------------------------------------------------------------------
__global__ __launch_bounds__(320) void k2_attn(const float* __restrict__ w_fc,
                                               const float* __restrict__ bn_gamma,
                                               const float* __restrict__ bn_beta,
                                               const float* __restrict__ bn_mean,
                                               const float* __restrict__ bn_var,
                                               const float* __restrict__ w_h,
                                               const float* __restrict__ w_w) {
    __shared__ float ys[MIP * L];        // swished bottleneck (5 KB)
    __shared__ float wfcT[C * MIP];      // w_fc transposed (8 KB)
    const int n = blockIdx.x;
    const int t = threadIdx.x;

    if (t < C) {
        #pragma unroll
        for (int m = 0; m < MIP; m++) wfcT[t * MIP + m] = w_fc[m * C + t];
    }
    __syncthreads();

    const float* __restrict__ yb = g_y + (size_t)n * C * L;
    if (t < L) {
        float acc[MIP];
        #pragma unroll
        for (int m = 0; m < MIP; m++) acc[m] = 0.f;
        #pragma unroll 4
        for (int c = 0; c < C; c++) {
            float v = yb[c * L + t];                     // coalesced across threads
            const float4* wr = (const float4*)(wfcT + c * MIP);
            float4 a = wr[0], b = wr[1];
            acc[0] = fmaf(a.x, v, acc[0]); acc[1] = fmaf(a.y, v, acc[1]);
            acc[2] = fmaf(a.z, v, acc[2]); acc[3] = fmaf(a.w, v, acc[3]);
            acc[4] = fmaf(b.x, v, acc[4]); acc[5] = fmaf(b.y, v, acc[5]);
            acc[6] = fmaf(b.z, v, acc[6]); acc[7] = fmaf(b.w, v, acc[7]);
        }
        #pragma unroll
        for (int m = 0; m < MIP; m++) {
            float iv = bn_gamma[m] * rsqrtf(bn_var[m] + BN_EPS);
            float vv = acc[m] * iv + (bn_beta[m] - bn_mean[m] * iv);
            ys[m * L + t] = vv * fsig(vv);
        }
    }
    __syncthreads();

    const int l  = t % 80;
    const int cg = t / 80;                               // 0..3
    const int c0 = (blockIdx.y * 4 + cg) * 32;
    float yh[MIP], yw[MIP];
    #pragma unroll
    for (int m = 0; m < MIP; m++) { yh[m] = ys[m * L + l]; yw[m] = ys[m * L + H + l]; }

    float* __restrict__ ahp = g_ah + (size_t)n * C * H;
    float* __restrict__ awp = g_aw + (size_t)n * C * W;
    #pragma unroll 4
    for (int c = c0; c < c0 + 32; c++) {
        const float4* wh4 = (const float4*)(w_h + c * MIP);
        const float4* ww4 = (const float4*)(w_w + c * MIP);
        float4 ha = wh4[0], hb = wh4[1];
        float4 wa = ww4[0], wb = ww4[1];
        float sh = 0.f, sw = 0.f;
        sh = fmaf(ha.x, yh[0], sh); sh = fmaf(ha.y, yh[1], sh);
        sh = fmaf(ha.z, yh[2], sh); sh = fmaf(ha.w, yh[3], sh);
        sh = fmaf(hb.x, yh[4], sh); sh = fmaf(hb.y, yh[5], sh);
        sh = fmaf(hb.z, yh[6], sh); sh = fmaf(hb.w, yh[7], sh);
        sw = fmaf(wa.x, yw[0], sw); sw = fmaf(wa.y, yw[1], sw);
        sw = fmaf(wa.z, yw[2], sw); sw = fmaf(wa.w, yw[3], sw);
        sw = fmaf(wb.x, yw[4], sw); sw = fmaf(wb.y, yw[5], sw);
        sw = fmaf(wb.z, yw[6], sw); sw = fmaf(wb.w, yw[7], sw);
        ahp[c * H + l] = fsig(sh);
        awp[c * W + l] = fsig(sw);
    }
}

// ---------------------------------------------------------------------------
// k3: single-wave grid-stride; exactly K3_ITER float4 per thread, unrolled.
// x read evict-first (__ldcs), out streaming store (__stcs) to preserve x in L2.
// ---------------------------------------------------------------------------
__global__ __launch_bounds__(K3_THR) void k3_apply(const float* __restrict__ x,
                                                   float* __restrict__ out) {
    const int base = blockIdx.x * K3_THR + threadIdx.x;
    const float4* __restrict__ x4 = (const float4*)x;
    float4* __restrict__ o4 = (float4*)out;

    #pragma unroll 4
    for (int k = 0; k < K3_ITER; k++) {
        const int i = base + k * K3_STRIDE;
        const int plane = i / 1600;                       // H*W/4
        const int rem   = i - plane * 1600;
        const int hh    = rem / 20;
        const int q     = rem - hh * 20;

        const float  ah  = __ldg(g_ah + plane * H + hh);
        const float4 aw4 = *((const float4*)g_aw + plane * 20 + q);
        const float4 xv  = __ldcs(x4 + i);

        float4 r;
        r.x = xv.x * (ah * aw4.x);
        r.y = xv.y * (ah * aw4.y);
        r.z = xv.z * (ah * aw4.z);
        r.w = xv.w * (ah * aw4.w);
        __stcs(o4 + i, r);
    }
}

// ---------------------------------------------------------------------------
extern "C" void kernel_launch(void* const* d_in, const int* in_sizes, int n_in,
                              void* d_out, int out_size) {
    const float* x        = (const float*)d_in[0];
    const float* w_fc     = (const float*)d_in[1];
    const float* bn_gamma = (const float*)d_in[2];
    const float* bn_beta  = (const float*)d_in[3];
    const float* bn_mean  = (const float*)d_in[4];
    const float* bn_var   = (const float*)d_in[5];
    const float* w_h      = (const float*)d_in[6];
    const float* w_w      = (const float*)d_in[7];
    float* out = (float*)d_out;

    k1_means<<<NB * C / K1_PPB, 320>>>(x);
    k2_attn<<<dim3(NB, 2), 320>>>(w_fc, bn_gamma, bn_beta, bn_mean, bn_var, w_h, w_w);
    k3_apply<<<K3_BLK, K3_THR>>>(x, out);
}

// round 7
// speedup vs baseline: 1.2993x; 1.2993x over previous
#include <cuda_runtime.h>
#include <math.h>

#define NB  16
#define C   256
#define H   80
#define W   80
#define MIP 8
#define L   160            // H + W
#define BN_EPS 1e-5f

// Scratch (device globals: no allocations allowed)
__device__ float g_y [NB * C * L];   // [n][c][l]: l<80 row means (x_h), l>=80 col means (x_w)
__device__ float g_ah[NB * C * H];
__device__ float g_aw[NB * C * W];

__device__ __forceinline__ float fsig(float v) { return 1.f / (1.f + __expf(-v)); }

// ---------------------------------------------------------------------------
// k1 (R3-proven form): one block (320 thr) per plane. 20 col-groups x 16
// row-groups; column partials in registers, tiny partials through padded smem.
// ---------------------------------------------------------------------------
__global__ __launch_bounds__(320) void k1_means(const float* __restrict__ x) {
    __shared__ float s_row[H][21];     // 21: gcd(21,32)=1
    __shared__ float s_col[W][17];     // 17: gcd(17,32)=1
    const int plane = blockIdx.x;
    const int t  = threadIdx.x;
    const int q  = t % 20;             // float4 column group
    const int rg = t / 20;             // row group 0..15
    const float4* __restrict__ xp = (const float4*)(x + (size_t)plane * (H * W));

    float4 cacc = make_float4(0.f, 0.f, 0.f, 0.f);
    #pragma unroll
    for (int i = 0; i < 5; i++) {
        int r = i * 16 + rg;
        float4 v = xp[r * 20 + q];
        cacc.x += v.x; cacc.y += v.y; cacc.z += v.z; cacc.w += v.w;
        s_row[r][q] = v.x + v.y + v.z + v.w;
    }
    s_col[4 * q + 0][rg] = cacc.x;
    s_col[4 * q + 1][rg] = cacc.y;
    s_col[4 * q + 2][rg] = cacc.z;
    s_col[4 * q + 3][rg] = cacc.w;
    __syncthreads();

    const float inv80 = 1.0f / 80.0f;
    if (t < H) {
        float s = 0.f;
        #pragma unroll
        for (int j = 0; j < 20; j++) s += s_row[t][j];
        g_y[(size_t)plane * L + t] = s * inv80;          // x_h (row mean)
    } else if (t >= 160 && t < 160 + W) {
        int col = t - 160;
        float s = 0.f;
        #pragma unroll
        for (int g = 0; g < 16; g++) s += s_col[col][g];
        g_y[(size_t)plane * L + H + col] = s * inv80;    // x_w (col mean)
    }
}

// ---------------------------------------------------------------------------
// k2: grid (16, 2), block 320.
// GEMM1 split-K: half = t/160 handles 128 channels, unroll 8 -> MLP 8.
// Partials combined through smem, then BN+swish. GEMM2 register-hoisted.
// ---------------------------------------------------------------------------
__global__ __launch_bounds__(320) void k2_attn(const float* __restrict__ w_fc,
                                               const float* __restrict__ bn_gamma,
                                               const float* __restrict__ bn_beta,
                                               const float* __restrict__ bn_mean,
                                               const float* __restrict__ bn_var,
                                               const float* __restrict__ w_h,
                                               const float* __restrict__ w_w) {
    __shared__ float ys[MIP * L];        // swished bottleneck (5 KB)
    __shared__ float wfcT[C * MIP];      // w_fc transposed (8 KB)
    __shared__ float ps[2 * MIP * L];    // split-K partials (10 KB)
    const int n = blockIdx.x;
    const int t = threadIdx.x;

    if (t < C) {
        #pragma unroll
        for (int m = 0; m < MIP; m++) wfcT[t * MIP + m] = w_fc[m * C + t];
    }
    __syncthreads();

    const float* __restrict__ yb = g_y + (size_t)n * C * L;
    {
        const int l    = t % L;
        const int half = t / L;                          // 0 or 1
        const int c0   = half * (C / 2);
        float acc[MIP];
        #pragma unroll
        for (int m = 0; m < MIP; m++) acc[m] = 0.f;
        #pragma unroll 8
        for (int c = 0; c < C / 2; c++) {
            float v = yb[(c0 + c) * L + l];              // coalesced across threads
            const float4* wr = (const float4*)(wfcT + (c0 + c) * MIP);
            float4 a = wr[0], b = wr[1];
            acc[0] = fmaf(a.x, v, acc[0]); acc[1] = fmaf(a.y, v, acc[1]);
            acc[2] = fmaf(a.z, v, acc[2]); acc[3] = fmaf(a.w, v, acc[3]);
            acc[4] = fmaf(b.x, v, acc[4]); acc[5] = fmaf(b.y, v, acc[5]);
            acc[6] = fmaf(b.z, v, acc[6]); acc[7] = fmaf(b.w, v, acc[7]);
        }
        #pragma unroll
        for (int m = 0; m < MIP; m++) ps[half * MIP * L + m * L + l] = acc[m];
    }
    __syncthreads();

    if (t < L) {
        #pragma unroll
        for (int m = 0; m < MIP; m++) {
            float s  = ps[m * L + t] + ps[MIP * L + m * L + t];
            float iv = bn_gamma[m] * rsqrtf(bn_var[m] + BN_EPS);
            float vv = s * iv + (bn_beta[m] - bn_mean[m] * iv);
            ys[m * L + t] = vv * fsig(vv);
        }
    }
    __syncthreads();

    const int l  = t % 80;
    const int cg = t / 80;                               // 0..3
    const int c0 = (blockIdx.y * 4 + cg) * 32;
    float yh[MIP], yw[MIP];
    #pragma unroll
    for (int m = 0; m < MIP; m++) { yh[m] = ys[m * L + l]; yw[m] = ys[m * L + H + l]; }

    float* __restrict__ ahp = g_ah + (size_t)n * C * H;
    float* __restrict__ awp = g_aw + (size_t)n * C * W;
    #pragma unroll 4
    for (int c = c0; c < c0 + 32; c++) {
        const float4* wh4 = (const float4*)(w_h + c * MIP);
        const float4* ww4 = (const float4*)(w_w + c * MIP);
        float4 ha = wh4[0], hb = wh4[1];
        float4 wa = ww4[0], wb = ww4[1];
        float sh = 0.f, sw = 0.f;
        sh = fmaf(ha.x, yh[0], sh); sh = fmaf(ha.y, yh[1], sh);
        sh = fmaf(ha.z, yh[2], sh); sh = fmaf(ha.w, yh[3], sh);
        sh = fmaf(hb.x, yh[4], sh); sh = fmaf(hb.y, yh[5], sh);
        sh = fmaf(hb.z, yh[6], sh); sh = fmaf(hb.w, yh[7], sh);
        sw = fmaf(wa.x, yw[0], sw); sw = fmaf(wa.y, yw[1], sw);
        sw = fmaf(wa.z, yw[2], sw); sw = fmaf(wa.w, yw[3], sw);
        sw = fmaf(wb.x, yw[4], sw); sw = fmaf(wb.y, yw[5], sw);
        sw = fmaf(wb.z, yw[6], sw); sw = fmaf(wb.w, yw[7], sw);
        ahp[c * H + l] = fsig(sh);
        awp[c * W + l] = fsig(sw);
    }
}

// ---------------------------------------------------------------------------
// k3: 1024 blocks x 256 thr. Each block owns 4 consecutive planes (6400 float4),
// processed in DESCENDING plane order (block 0 -> highest planes) so reads chase
// the most-recently-cached x lines. Attention maps staged in smem (race-free
// strided loop this time); inner loop is a pure x-stream with 5 front-batched
// LDG.128 per batch. Streaming stores for the out write.
// ---------------------------------------------------------------------------
__global__ __launch_bounds__(256) void k3_apply(const float* __restrict__ x,
                                                float* __restrict__ out) {
    __shared__ float  s_ah[4 * H];       // 4 planes of a_h (320 floats)
    __shared__ float4 s_aw[4 * 20];      // 4 planes of a_w as float4 (80 entries)
    const int pb  = 1023 - blockIdx.x;   // 4-plane group, descending
    const int tid = threadIdx.x;
    const size_t base = (size_t)pb * 6400;   // float4 base

    // Stage attention maps for the 4 planes (race-free, full coverage)
    for (int i = tid; i < 4 * H; i += 256)
        s_ah[i] = g_ah[pb * 4 * H + i];
    if (tid < 4 * 20)
        s_aw[tid] = ((const float4*)g_aw)[pb * 4 * 20 + tid];
    __syncthreads();

    const float4* __restrict__ x4 = (const float4*)x;
    float4* __restrict__ o4 = (float4*)out;

    #pragma unroll
    for (int batch = 0; batch < 5; batch++) {
        float4 xv[5];
        int    idx[5];
        #pragma unroll
        for (int jj = 0; jj < 5; jj++) {
            idx[jj] = (batch * 5 + jj) * 256 + tid;      // [0, 6400)
            xv[jj]  = x4[base + idx[jj]];
        }
        #pragma unroll
        for (int jj = 0; jj < 5; jj++) {
            const int v   = idx[jj];
            const int lp  = v / 1600;                    // local plane 0..3
            const int rem = v - lp * 1600;
            const int hh  = rem / 20;
            const int q   = rem - hh * 20;
            const float  ah  = s_ah[lp * H + hh];
            const float4 aw4 = s_aw[lp * 20 + q];
            float4 r;
            r.x = xv[jj].x * (ah * aw4.x);
            r.y = xv[jj].y * (ah * aw4.y);
            r.z = xv[jj].z * (ah * aw4.z);
            r.w = xv[jj].w * (ah * aw4.w);
            __stcs(o4 + base + v, r);
        }
    }
}

// ---------------------------------------------------------------------------
extern "C" void kernel_launch(void* const* d_in, const int* in_sizes, int n_in,
                              void* d_out, int out_size) {
    const float* x        = (const float*)d_in[0];
    const float* w_fc     = (const float*)d_in[1];
    const float* bn_gamma = (const float*)d_in[2];
    const float* bn_beta  = (const float*)d_in[3];
    const float* bn_mean  = (const float*)d_in[4];
    const float* bn_var   = (const float*)d_in[5];
    const float* w_h      = (const float*)d_in[6];
    const float* w_w      = (const float*)d_in[7];
    float* out = (float*)d_out;

    k1_means<<<NB * C, 320>>>(x);
    k2_attn<<<dim3(NB, 2), 320>>>(w_fc, bn_gamma, bn_beta, bn_mean, bn_var, w_h, w_w);
    k3_apply<<<1024, 256>>>(x, out);
}